// round 1
// baseline (speedup 1.0000x reference)
#include <cuda_runtime.h>
#include <math.h>

#define N_HITS   16384
#define N_EDGES  262144
#define N_GROUPS 512
#define HID      128
#define HEADS    4
#define DH       32
#define LAYERS   3
#define EDGE_DIM 5
#define FFN_DIM  512
#define LN_EPS   1e-5f

// ---------------- scratch (static device globals; no allocation) ----------------
__device__ float g_h   [N_HITS * HID];
__device__ float g_qkv [N_HITS * 3 * HID];
__device__ float g_attn[N_HITS * HID];
__device__ float g_ffn [N_HITS * FFN_DIM];
__device__ float g_tmp [N_HITS * HID];
__device__ int   g_deg [N_HITS];
__device__ int   g_rowptr[N_HITS + 1];
__device__ int   g_cursor[N_HITS];
__device__ int   g_eid [N_EDGES];
__device__ int   g_esrc[N_EDGES];
__device__ float g_gmax[N_GROUPS * HID];
__device__ float g_gsum[2 * N_GROUPS * HID];
__device__ float g_cnt [3 * N_GROUPS];           // [view0 | view1 | all]
__device__ float g_ge  [N_GROUPS * 2 * HID];
__device__ float g_Aaf [N_GROUPS * HID];
__device__ float g_Baf [N_GROUPS * HID];
__device__ float g_sc  [N_GROUPS * N_GROUPS];

// ---------------- helpers ----------------
__device__ __forceinline__ void atomicMaxFloat(float* addr, float value) {
    if (value >= 0.f)
        atomicMax((int*)addr, __float_as_int(value));
    else
        atomicMin((unsigned int*)addr, __float_as_uint(value));
}

// ---------------- CSR build ----------------
__global__ void zero_deg_kernel() {
    int i = blockIdx.x * blockDim.x + threadIdx.x;
    if (i < N_HITS) g_deg[i] = 0;
}

__global__ void hist_kernel(const int* __restrict__ ei) {
    int e = blockIdx.x * blockDim.x + threadIdx.x;
    if (e < N_EDGES) atomicAdd(&g_deg[ei[N_EDGES + e]], 1);
}

__global__ void scan_kernel() {
    __shared__ int sh[1024];
    __shared__ int carry;
    int tid = threadIdx.x;
    if (tid == 0) carry = 0;
    __syncthreads();
    for (int base = 0; base < N_HITS; base += 1024) {
        int v = g_deg[base + tid];
        sh[tid] = v;
        __syncthreads();
        for (int off = 1; off < 1024; off <<= 1) {
            int t = (tid >= off) ? sh[tid - off] : 0;
            __syncthreads();
            sh[tid] += t;
            __syncthreads();
        }
        g_rowptr[base + tid] = carry + sh[tid] - v;   // exclusive
        __syncthreads();
        if (tid == 1023) carry += sh[1023];
        __syncthreads();
    }
    if (tid == 0) g_rowptr[N_HITS] = carry;
}

__global__ void copy_cursor_kernel() {
    int i = blockIdx.x * blockDim.x + threadIdx.x;
    if (i < N_HITS) g_cursor[i] = g_rowptr[i];
}

__global__ void scatter_kernel(const int* __restrict__ ei) {
    int e = blockIdx.x * blockDim.x + threadIdx.x;
    if (e < N_EDGES) {
        int dstn = ei[N_EDGES + e];
        int pos = atomicAdd(&g_cursor[dstn], 1);
        g_eid[pos]  = e;
        g_esrc[pos] = ei[e];
    }
}

// ---------------- embed: h = x @ W(25x128) + b ----------------
__global__ void __launch_bounds__(128) embed_kernel(
    const float* __restrict__ x, const float* __restrict__ W, const float* __restrict__ b)
{
    __shared__ float sW[25 * 128];
    __shared__ float sx[8][25];
    int tid = threadIdx.x;
    for (int i = tid; i < 25 * 128; i += 128) sW[i] = W[i];
    int r0 = blockIdx.x * 8;
    for (int i = tid; i < 8 * 25; i += 128)
        sx[i / 25][i % 25] = x[(size_t)(r0 + i / 25) * 25 + (i % 25)];
    __syncthreads();
    float bb = b[tid];
    for (int r = 0; r < 8; r++) {
        float acc = bb;
        #pragma unroll
        for (int c = 0; c < 25; c++) acc = fmaf(sx[r][c], sW[c * 128 + tid], acc);
        g_h[(size_t)(r0 + r) * 128 + tid] = acc;
    }
}

// ---------------- generic SGEMM: C = A[MxK] @ B[KxN] (+bias)(+relu) ----------------
// requires M%64==0, N%64==0, K%16==0
__global__ void __launch_bounds__(256) sgemm_kernel(
    const float* __restrict__ A, const float* __restrict__ B,
    const float* __restrict__ bias, float* __restrict__ C,
    int M, int N, int K, int relu)
{
    __shared__ float sA[64][17];
    __shared__ float sB[16][64];
    const int tid = threadIdx.x;
    const int tx = tid & 15;
    const int ty = tid >> 4;
    const int m0 = blockIdx.y << 6;
    const int n0 = blockIdx.x << 6;
    const int arow = tid >> 2,  acol = (tid & 3) << 2;
    const int brow = tid >> 4,  bcol = (tid & 15) << 2;
    float acc[4][4];
    #pragma unroll
    for (int i = 0; i < 4; i++)
        #pragma unroll
        for (int j = 0; j < 4; j++) acc[i][j] = 0.f;

    for (int k0 = 0; k0 < K; k0 += 16) {
        float4 av = *(const float4*)(A + (size_t)(m0 + arow) * K + k0 + acol);
        float4 bv = *(const float4*)(B + (size_t)(k0 + brow) * N + n0 + bcol);
        sA[arow][acol + 0] = av.x; sA[arow][acol + 1] = av.y;
        sA[arow][acol + 2] = av.z; sA[arow][acol + 3] = av.w;
        sB[brow][bcol + 0] = bv.x; sB[brow][bcol + 1] = bv.y;
        sB[brow][bcol + 2] = bv.z; sB[brow][bcol + 3] = bv.w;
        __syncthreads();
        #pragma unroll
        for (int k = 0; k < 16; k++) {
            float a[4], b[4];
            #pragma unroll
            for (int i = 0; i < 4; i++) a[i] = sA[(ty << 2) + i][k];
            #pragma unroll
            for (int j = 0; j < 4; j++) b[j] = sB[k][tx + (j << 4)];
            #pragma unroll
            for (int i = 0; i < 4; i++)
                #pragma unroll
                for (int j = 0; j < 4; j++) acc[i][j] = fmaf(a[i], b[j], acc[i][j]);
        }
        __syncthreads();
    }
    #pragma unroll
    for (int i = 0; i < 4; i++) {
        int m = m0 + (ty << 2) + i;
        #pragma unroll
        for (int j = 0; j < 4; j++) {
            int n = n0 + tx + (j << 4);
            float r = acc[i][j];
            if (bias) r += bias[n];
            if (relu) r = fmaxf(r, 0.f);
            C[(size_t)m * N + n] = r;
        }
    }
}

// ---------------- edge attention: one warp per destination node, online softmax ----------------
__global__ void __launch_bounds__(256) attn_kernel(
    const float* __restrict__ edge_attr,
    const float* __restrict__ We, const float* __restrict__ be)
{
    const int node = (blockIdx.x * 256 + threadIdx.x) >> 5;
    const int lane = threadIdx.x & 31;
    if (node >= N_HITS) return;

    float Wer[EDGE_DIM][4], ber[4], qr[4];
    #pragma unroll
    for (int j = 0; j < 4; j++) {
        int d = lane + 32 * j;
        ber[j] = be[d];
        #pragma unroll
        for (int c = 0; c < EDGE_DIM; c++) Wer[c][j] = We[c * HID + d];
        qr[j] = g_qkv[(size_t)node * 384 + d];
    }
    float m[4], s[4], acc[4];
    #pragma unroll
    for (int j = 0; j < 4; j++) { m[j] = -INFINITY; s[j] = 0.f; acc[j] = 0.f; }

    const int beg = g_rowptr[node], end = g_rowptr[node + 1];
    const float scale = 0.17677669529663687f;   // 1/sqrt(32)

    for (int idx = beg; idx < end; idx++) {
        int eid = g_eid[idx];
        int src = g_esrc[idx];
        float ea[EDGE_DIM];
        #pragma unroll
        for (int c = 0; c < EDGE_DIM; c++) ea[c] = edge_attr[(size_t)eid * EDGE_DIM + c];
        float prod[4], vs[4];
        #pragma unroll
        for (int j = 0; j < 4; j++) {
            int d = lane + 32 * j;
            float e = ber[j];
            #pragma unroll
            for (int c = 0; c < EDGE_DIM; c++) e = fmaf(ea[c], Wer[c][j], e);
            float kk = g_qkv[(size_t)src * 384 + 128 + d] + e;
            float vv = g_qkv[(size_t)src * 384 + 256 + d] + e;
            prod[j] = qr[j] * kk;
            vs[j] = vv;
        }
        #pragma unroll
        for (int off = 16; off; off >>= 1) {
            #pragma unroll
            for (int j = 0; j < 4; j++)
                prod[j] += __shfl_xor_sync(0xffffffffu, prod[j], off);
        }
        #pragma unroll
        for (int j = 0; j < 4; j++) {
            float logit = prod[j] * scale;
            float mn = fmaxf(m[j], logit);
            float corr = __expf(m[j] - mn);   // exp(-inf)=0 on first edge
            float p = __expf(logit - mn);
            s[j]   = s[j] * corr + p;
            acc[j] = acc[j] * corr + p * vs[j];
            m[j] = mn;
        }
    }
    #pragma unroll
    for (int j = 0; j < 4; j++)
        g_attn[(size_t)node * 128 + lane + 32 * j] = acc[j] / fmaxf(s[j], 1e-9f);
}

// ---------------- layernorm: h = LN(h + tmp) * g + b ; one warp per row ----------------
__global__ void __launch_bounds__(256) ln_kernel(
    const float* __restrict__ gam, const float* __restrict__ bet)
{
    const int row = (blockIdx.x * 256 + threadIdx.x) >> 5;
    const int lane = threadIdx.x & 31;
    if (row >= N_HITS) return;
    float v[4];
    float sum = 0.f;
    #pragma unroll
    for (int j = 0; j < 4; j++) {
        int d = lane + 32 * j;
        v[j] = g_h[(size_t)row * 128 + d] + g_tmp[(size_t)row * 128 + d];
        sum += v[j];
    }
    #pragma unroll
    for (int off = 16; off; off >>= 1) sum += __shfl_xor_sync(0xffffffffu, sum, off);
    float mu = sum * (1.f / 128.f);
    float vs = 0.f;
    #pragma unroll
    for (int j = 0; j < 4; j++) { float t = v[j] - mu; vs += t * t; }
    #pragma unroll
    for (int off = 16; off; off >>= 1) vs += __shfl_xor_sync(0xffffffffu, vs, off);
    float rstd = rsqrtf(vs * (1.f / 128.f) + LN_EPS);
    #pragma unroll
    for (int j = 0; j < 4; j++) {
        int d = lane + 32 * j;
        g_h[(size_t)row * 128 + d] = (v[j] - mu) * rstd * gam[d] + bet[d];
    }
}

// ---------------- group pooling ----------------
__global__ void pool_init_kernel() {
    int i = blockIdx.x * blockDim.x + threadIdx.x;
    int stride = gridDim.x * blockDim.x;
    for (int k = i; k < N_GROUPS * HID; k += stride)     g_gmax[k] = -INFINITY;
    for (int k = i; k < 2 * N_GROUPS * HID; k += stride) g_gsum[k] = 0.f;
    for (int k = i; k < 3 * N_GROUPS; k += stride)       g_cnt[k]  = 0.f;
}

__global__ void __launch_bounds__(128) pool_scatter_kernel(
    const float* __restrict__ x, const int* __restrict__ grp)
{
    int hit = blockIdx.x;
    int d = threadIdx.x;
    int g = grp[hit];
    float val = g_h[(size_t)hit * 128 + d];
    atomicMaxFloat(&g_gmax[g * 128 + d], val);
    int view = (int)x[(size_t)hit * 25 + 3];   // truncation toward zero like astype(int32)
    if (view == 0 || view == 1)
        atomicAdd(&g_gsum[view * N_GROUPS * HID + g * 128 + d], val);
    if (d == 0) {
        atomicAdd(&g_cnt[2 * N_GROUPS + g], 1.f);
        if (view == 0 || view == 1) atomicAdd(&g_cnt[view * N_GROUPS + g], 1.f);
    }
}

__global__ void __launch_bounds__(128) pool_finalize_kernel() {
    int g = blockIdx.x;
    int d = threadIdx.x;
    float cx = g_cnt[g], cy = g_cnt[N_GROUPS + g], ca = g_cnt[2 * N_GROUPS + g];
    float sx = g_gsum[g * 128 + d];
    float sy = g_gsum[N_GROUPS * HID + g * 128 + d];
    float px = sx / fmaxf(cx, 1.f);
    float py = sy / fmaxf(cy, 1.f);
    float hx = (cx > 0.f) ? 1.f : 0.f;
    float hy = (cy > 0.f) ? 1.f : 0.f;
    float sum_feat = px * hx + py * hy;
    float valid = fmaxf(hx + hy, 1.f);
    g_ge[g * 256 + d] = sum_feat / valid;
    g_ge[g * 256 + 128 + d] = (ca > 0.f) ? g_gmax[g * 128 + d] : 0.f;
}

// ---------------- pairwise affinity scores ----------------
__global__ void __launch_bounds__(256) scores_kernel(
    const float* __restrict__ b1, const float* __restrict__ W2, const float* __restrict__ b2)
{
    __shared__ float sA[16][129];
    __shared__ float sB[16][129];
    __shared__ float sb1[128];
    __shared__ float sW2[128];
    int tx = threadIdx.x, ty = threadIdx.y;
    int tid = ty * 16 + tx;
    int i0 = blockIdx.y * 16, j0 = blockIdx.x * 16;
    for (int t = tid; t < 16 * 128; t += 256) {
        sA[t >> 7][t & 127] = g_Aaf[(i0 + (t >> 7)) * 128 + (t & 127)];
        sB[t >> 7][t & 127] = g_Baf[(j0 + (t >> 7)) * 128 + (t & 127)];
    }
    if (tid < 128) { sb1[tid] = b1[tid]; sW2[tid] = W2[tid]; }
    __syncthreads();
    float acc = 0.f;
    #pragma unroll 8
    for (int d = 0; d < 128; d++) {
        float pre = sA[ty][d] + sB[tx][d] + sb1[d];
        acc = fmaf(fmaxf(pre, 0.f), sW2[d], acc);
    }
    g_sc[(size_t)(i0 + ty) * N_GROUPS + (j0 + tx)] = acc + b2[0];
}

__global__ void final_kernel(const int* __restrict__ batch, float* __restrict__ out) {
    int idx = blockIdx.x * blockDim.x + threadIdx.x;
    if (idx >= N_GROUPS * N_GROUPS) return;
    int i = idx >> 9, j = idx & 511;
    float sc = 0.5f * (g_sc[(size_t)i * N_GROUPS + j] + g_sc[(size_t)j * N_GROUPS + i]);
    float mask = (batch[i] == batch[j]) ? 1.f : 0.f;
    out[idx] = mask / (1.f + expf(-sc));
}

// ---------------- launch ----------------
extern "C" void kernel_launch(void* const* d_in, const int* in_sizes, int n_in,
                              void* d_out, int out_size)
{
    const float* x          = (const float*)d_in[0];
    const int*   edge_index = (const int*)  d_in[1];
    const float* edge_attr  = (const float*)d_in[2];
    const int*   grp        = (const int*)  d_in[3];
    const int*   batch      = (const int*)  d_in[4];
    const float* embed_W    = (const float*)d_in[5];
    const float* embed_b    = (const float*)d_in[6];
    const float* Wqkv       = (const float*)d_in[7];
    const float* bqkv       = (const float*)d_in[8];
    const float* We         = (const float*)d_in[9];
    const float* be         = (const float*)d_in[10];
    const float* Wo         = (const float*)d_in[11];
    const float* bo         = (const float*)d_in[12];
    const float* ln1g       = (const float*)d_in[13];
    const float* ln1b       = (const float*)d_in[14];
    const float* W1         = (const float*)d_in[15];
    const float* b1         = (const float*)d_in[16];
    const float* W2         = (const float*)d_in[17];
    const float* b2         = (const float*)d_in[18];
    const float* ln2g       = (const float*)d_in[19];
    const float* ln2b       = (const float*)d_in[20];
    const float* affW1      = (const float*)d_in[21];
    const float* affb1      = (const float*)d_in[22];
    const float* affW2      = (const float*)d_in[23];
    const float* affb2      = (const float*)d_in[24];
    float* out = (float*)d_out;

    float *p_h, *p_qkv, *p_attn, *p_ffn, *p_tmp, *p_ge, *p_A, *p_B;
    cudaGetSymbolAddress((void**)&p_h,    g_h);
    cudaGetSymbolAddress((void**)&p_qkv,  g_qkv);
    cudaGetSymbolAddress((void**)&p_attn, g_attn);
    cudaGetSymbolAddress((void**)&p_ffn,  g_ffn);
    cudaGetSymbolAddress((void**)&p_tmp,  g_tmp);
    cudaGetSymbolAddress((void**)&p_ge,   g_ge);
    cudaGetSymbolAddress((void**)&p_A,    g_Aaf);
    cudaGetSymbolAddress((void**)&p_B,    g_Baf);

    // CSR build (edge_index is an input; rebuild every call, it is cheap)
    zero_deg_kernel<<<N_HITS / 256, 256>>>();
    hist_kernel<<<N_EDGES / 256, 256>>>(edge_index);
    scan_kernel<<<1, 1024>>>();
    copy_cursor_kernel<<<N_HITS / 256, 256>>>();
    scatter_kernel<<<N_EDGES / 256, 256>>>(edge_index);

    // embed
    embed_kernel<<<N_HITS / 8, 128>>>(x, embed_W, embed_b);

    for (int l = 0; l < LAYERS; l++) {
        // qkv = h @ Wqkv + b
        sgemm_kernel<<<dim3(384 / 64, N_HITS / 64), 256>>>(
            p_h, Wqkv + (size_t)l * HID * 3 * HID, bqkv + l * 3 * HID, p_qkv,
            N_HITS, 3 * HID, HID, 0);
        // edge attention -> g_attn
        attn_kernel<<<N_HITS / 8, 256>>>(edge_attr,
            We + (size_t)l * EDGE_DIM * HID, be + l * HID);
        // attn @ Wo + bo -> tmp
        sgemm_kernel<<<dim3(HID / 64, N_HITS / 64), 256>>>(
            p_attn, Wo + (size_t)l * HID * HID, bo + l * HID, p_tmp,
            N_HITS, HID, HID, 0);
        // h = LN1(h + tmp)
        ln_kernel<<<N_HITS / 8, 256>>>(ln1g + l * HID, ln1b + l * HID);
        // ffn hidden = relu(h @ W1 + b1)
        sgemm_kernel<<<dim3(FFN_DIM / 64, N_HITS / 64), 256>>>(
            p_h, W1 + (size_t)l * HID * FFN_DIM, b1 + l * FFN_DIM, p_ffn,
            N_HITS, FFN_DIM, HID, 1);
        // tmp = ffn @ W2 + b2
        sgemm_kernel<<<dim3(HID / 64, N_HITS / 64), 256>>>(
            p_ffn, W2 + (size_t)l * FFN_DIM * HID, b2 + l * HID, p_tmp,
            N_HITS, HID, FFN_DIM, 0);
        // h = LN2(h + tmp)
        ln_kernel<<<N_HITS / 8, 256>>>(ln2g + l * HID, ln2b + l * HID);
    }

    // pooling -> ge [512, 256]
    pool_init_kernel<<<256, 256>>>();
    pool_scatter_kernel<<<N_HITS, 128>>>(x, grp);
    pool_finalize_kernel<<<N_GROUPS, 128>>>();

    // affinity: A = ge @ W1a, B = ge @ W1b   (bias folded into scores kernel)
    sgemm_kernel<<<dim3(HID / 64, N_GROUPS / 64), 256>>>(
        p_ge, affW1, nullptr, p_A, N_GROUPS, HID, 2 * HID, 0);
    sgemm_kernel<<<dim3(HID / 64, N_GROUPS / 64), 256>>>(
        p_ge, affW1 + (size_t)2 * HID * HID, nullptr, p_B, N_GROUPS, HID, 2 * HID, 0);

    scores_kernel<<<dim3(N_GROUPS / 16, N_GROUPS / 16), dim3(16, 16)>>>(affb1, affW2, affb2);
    final_kernel<<<(N_GROUPS * N_GROUPS) / 256, 256>>>(batch, out);
}

// round 2
// speedup vs baseline: 1.1090x; 1.1090x over previous
#include <cuda_runtime.h>
#include <math.h>
#include <stdint.h>

#define N_HITS   16384
#define N_EDGES  262144
#define N_GROUPS 512
#define HID      128
#define HEADS    4
#define DH       32
#define LAYERS   3
#define EDGE_DIM 5
#define FFN_DIM  512
#define LN_EPS   1e-5f

// ---------------- scratch (static device globals; no allocation) ----------------
__device__ float g_h   [N_HITS * HID];
__device__ float g_qkv [N_HITS * 3 * HID];
__device__ float g_attn[N_HITS * HID];
__device__ float g_ffn [N_HITS * FFN_DIM];
__device__ float g_tmp [N_HITS * HID];
__device__ int   g_deg [N_HITS];
__device__ int   g_rowptr[N_HITS + 1];
__device__ int   g_cursor[N_HITS];
__device__ int   g_eid [N_EDGES];
__device__ int   g_esrc[N_EDGES];
__device__ float g_gmax[N_GROUPS * HID];
__device__ float g_gsum[2 * N_GROUPS * HID];
__device__ float g_cnt [3 * N_GROUPS];           // [view0 | view1 | all]
__device__ float g_ge  [N_GROUPS * 2 * HID];
__device__ float g_Aaf [N_GROUPS * HID];
__device__ float g_Baf [N_GROUPS * HID];
__device__ float g_sc  [N_GROUPS * N_GROUPS];

// ---------------- helpers ----------------
__device__ __forceinline__ void atomicMaxFloat(float* addr, float value) {
    if (value >= 0.f)
        atomicMax((int*)addr, __float_as_int(value));
    else
        atomicMin((unsigned int*)addr, __float_as_uint(value));
}

__device__ __forceinline__ float to_tf32(float x) {
    uint32_t u;
    asm("cvt.rna.tf32.f32 %0, %1;" : "=r"(u) : "f"(x));
    return __uint_as_float(u);
}

__device__ __forceinline__ void mma_tf32(float* d, const uint32_t* a, const uint32_t* b) {
    asm volatile(
        "mma.sync.aligned.m16n8k8.row.col.f32.tf32.tf32.f32 "
        "{%0,%1,%2,%3}, {%4,%5,%6,%7}, {%8,%9}, {%0,%1,%2,%3};"
        : "+f"(d[0]), "+f"(d[1]), "+f"(d[2]), "+f"(d[3])
        : "r"(a[0]), "r"(a[1]), "r"(a[2]), "r"(a[3]),
          "r"(b[0]), "r"(b[1]));
}

// ---------------- CSR build ----------------
__global__ void zero_deg_kernel() {
    int i = blockIdx.x * blockDim.x + threadIdx.x;
    if (i < N_HITS) g_deg[i] = 0;
}

__global__ void hist_kernel(const int* __restrict__ ei) {
    int e = blockIdx.x * blockDim.x + threadIdx.x;
    if (e < N_EDGES) atomicAdd(&g_deg[ei[N_EDGES + e]], 1);
}

__global__ void scan_kernel() {
    __shared__ int sh[1024];
    __shared__ int carry;
    int tid = threadIdx.x;
    if (tid == 0) carry = 0;
    __syncthreads();
    for (int base = 0; base < N_HITS; base += 1024) {
        int v = g_deg[base + tid];
        sh[tid] = v;
        __syncthreads();
        for (int off = 1; off < 1024; off <<= 1) {
            int t = (tid >= off) ? sh[tid - off] : 0;
            __syncthreads();
            sh[tid] += t;
            __syncthreads();
        }
        g_rowptr[base + tid] = carry + sh[tid] - v;   // exclusive
        __syncthreads();
        if (tid == 1023) carry += sh[1023];
        __syncthreads();
    }
    if (tid == 0) g_rowptr[N_HITS] = carry;
}

__global__ void copy_cursor_kernel() {
    int i = blockIdx.x * blockDim.x + threadIdx.x;
    if (i < N_HITS) g_cursor[i] = g_rowptr[i];
}

__global__ void scatter_kernel(const int* __restrict__ ei) {
    int e = blockIdx.x * blockDim.x + threadIdx.x;
    if (e < N_EDGES) {
        int dstn = ei[N_EDGES + e];
        int pos = atomicAdd(&g_cursor[dstn], 1);
        g_eid[pos]  = e;
        g_esrc[pos] = ei[e];
    }
}

// ---------------- embed: h = x @ W(25x128) + b ----------------
__global__ void __launch_bounds__(128) embed_kernel(
    const float* __restrict__ x, const float* __restrict__ W, const float* __restrict__ b)
{
    __shared__ float sW[25 * 128];
    __shared__ float sx[8][25];
    int tid = threadIdx.x;
    for (int i = tid; i < 25 * 128; i += 128) sW[i] = W[i];
    int r0 = blockIdx.x * 8;
    for (int i = tid; i < 8 * 25; i += 128)
        sx[i / 25][i % 25] = x[(size_t)(r0 + i / 25) * 25 + (i % 25)];
    __syncthreads();
    float bb = b[tid];
    for (int r = 0; r < 8; r++) {
        float acc = bb;
        #pragma unroll
        for (int c = 0; c < 25; c++) acc = fmaf(sx[r][c], sW[c * 128 + tid], acc);
        g_h[(size_t)(r0 + r) * 128 + tid] = acc;
    }
}

// ---------------- TF32 tensor-core GEMM: C = A[MxK] @ B[KxN] (+bias)(+relu) ----------------
// BM=128, BN=128, BK=16, 256 threads (8 warps, 2x4), warp tile 64x32 via m16n8k8.
// requires M%128==0, N%128==0, K%16==0
#define GBM 128
#define GBN 128
#define GBK 16

__global__ void __launch_bounds__(256) tf32_gemm_kernel(
    const float* __restrict__ A, const float* __restrict__ B,
    const float* __restrict__ bias, float* __restrict__ C,
    int M, int N, int K, int relu)
{
    __shared__ float sA[GBM][GBK + 4];   // row stride 20 floats -> conflict-free frag loads
    __shared__ float sB[GBK][GBN + 8];   // row stride 136 floats

    const int tid  = threadIdx.x;
    const int wid  = tid >> 5;
    const int lane = tid & 31;
    const int wm   = wid & 1;            // 0..1 : 64-row slab
    const int wn   = wid >> 1;           // 0..3 : 32-col slab
    const int g    = lane >> 2;          // 0..7
    const int r    = lane & 3;           // 0..3

    const int m0 = blockIdx.y * GBM;
    const int n0 = blockIdx.x * GBN;

    // global->smem mapping for A: each thread: row = tid>>1, khalf = (tid&1)*8, two float4
    const int a_row   = tid >> 1;
    const int a_khalf = (tid & 1) * 8;

    float acc[4][4][4];
    #pragma unroll
    for (int mt = 0; mt < 4; mt++)
        #pragma unroll
        for (int nt = 0; nt < 4; nt++)
            #pragma unroll
            for (int i = 0; i < 4; i++) acc[mt][nt][i] = 0.f;

    for (int k0 = 0; k0 < K; k0 += GBK) {
        // load A tile (transposed to tf32 in smem, layout [m][k])
        {
            const float* Ap = A + (size_t)(m0 + a_row) * K + k0 + a_khalf;
            float4 v0 = *(const float4*)(Ap);
            float4 v1 = *(const float4*)(Ap + 4);
            float4 w0 = make_float4(to_tf32(v0.x), to_tf32(v0.y), to_tf32(v0.z), to_tf32(v0.w));
            float4 w1 = make_float4(to_tf32(v1.x), to_tf32(v1.y), to_tf32(v1.z), to_tf32(v1.w));
            *(float4*)&sA[a_row][a_khalf]     = w0;
            *(float4*)&sA[a_row][a_khalf + 4] = w1;
        }
        // load B tile [k][n]
        #pragma unroll
        for (int i = 0; i < 2; i++) {
            int id  = tid + 256 * i;           // 0..511
            int row = id >> 5;                  // 0..15
            int c4  = (id & 31) * 4;            // 0..124
            float4 v = *(const float4*)(B + (size_t)(k0 + row) * N + n0 + c4);
            float4 w = make_float4(to_tf32(v.x), to_tf32(v.y), to_tf32(v.z), to_tf32(v.w));
            *(float4*)&sB[row][c4] = w;
        }
        __syncthreads();

        #pragma unroll
        for (int ks = 0; ks < 2; ks++) {
            const int kk = ks * 8;
            uint32_t af[4][4], bf[4][2];
            #pragma unroll
            for (int mt = 0; mt < 4; mt++) {
                int rb = wm * 64 + mt * 16;
                af[mt][0] = __float_as_uint(sA[rb + g    ][kk + r    ]);
                af[mt][1] = __float_as_uint(sA[rb + g + 8][kk + r    ]);
                af[mt][2] = __float_as_uint(sA[rb + g    ][kk + r + 4]);
                af[mt][3] = __float_as_uint(sA[rb + g + 8][kk + r + 4]);
            }
            #pragma unroll
            for (int nt = 0; nt < 4; nt++) {
                int cb = wn * 32 + nt * 8;
                bf[nt][0] = __float_as_uint(sB[kk + r    ][cb + g]);
                bf[nt][1] = __float_as_uint(sB[kk + r + 4][cb + g]);
            }
            #pragma unroll
            for (int mt = 0; mt < 4; mt++)
                #pragma unroll
                for (int nt = 0; nt < 4; nt++)
                    mma_tf32(acc[mt][nt], af[mt], bf[nt]);
        }
        __syncthreads();
    }

    // epilogue: c0 (row g, col 2r), c1 (+1), c2 (row g+8), c3 (+1)
    #pragma unroll
    for (int mt = 0; mt < 4; mt++) {
        int row_a = m0 + wm * 64 + mt * 16 + g;
        int row_b = row_a + 8;
        #pragma unroll
        for (int nt = 0; nt < 4; nt++) {
            int col = n0 + wn * 32 + nt * 8 + 2 * r;
            float b0 = 0.f, b1 = 0.f;
            if (bias) { b0 = bias[col]; b1 = bias[col + 1]; }
            float v0 = acc[mt][nt][0] + b0;
            float v1 = acc[mt][nt][1] + b1;
            float v2 = acc[mt][nt][2] + b0;
            float v3 = acc[mt][nt][3] + b1;
            if (relu) {
                v0 = fmaxf(v0, 0.f); v1 = fmaxf(v1, 0.f);
                v2 = fmaxf(v2, 0.f); v3 = fmaxf(v3, 0.f);
            }
            *(float2*)&C[(size_t)row_a * N + col] = make_float2(v0, v1);
            *(float2*)&C[(size_t)row_b * N + col] = make_float2(v2, v3);
        }
    }
}

// ---------------- edge attention: one warp per destination node, online softmax ----------------
// lane owns dims [4*lane, 4*lane+4); head = lane>>3; reduce within 8-lane head groups.
__global__ void __launch_bounds__(256) attn_kernel(
    const float* __restrict__ edge_attr,
    const float* __restrict__ We, const float* __restrict__ be)
{
    const int node = (blockIdx.x * 256 + threadIdx.x) >> 5;
    const int lane = threadIdx.x & 31;
    if (node >= N_HITS) return;

    const int d0 = 4 * lane;
    float Wer[EDGE_DIM][4], ber[4];
    #pragma unroll
    for (int c = 0; c < 4; c++) {
        ber[c] = be[d0 + c];
        #pragma unroll
        for (int cc = 0; cc < EDGE_DIM; cc++) Wer[cc][c] = We[cc * HID + d0 + c];
    }
    float4 q = *(const float4*)&g_qkv[(size_t)node * 384 + d0];

    float m = -INFINITY, s = 0.f;
    float acc[4] = {0.f, 0.f, 0.f, 0.f};

    const int beg = g_rowptr[node], end = g_rowptr[node + 1];
    const float scale = 0.17677669529663687f;   // 1/sqrt(32)

    for (int idx = beg; idx < end; idx++) {
        int eid = g_eid[idx];
        int src = g_esrc[idx];
        float ea[EDGE_DIM];
        #pragma unroll
        for (int cc = 0; cc < EDGE_DIM; cc++) ea[cc] = edge_attr[(size_t)eid * EDGE_DIM + cc];
        float4 kk = *(const float4*)&g_qkv[(size_t)src * 384 + 128 + d0];
        float4 vv = *(const float4*)&g_qkv[(size_t)src * 384 + 256 + d0];

        float e[4];
        #pragma unroll
        for (int c = 0; c < 4; c++) {
            float t = ber[c];
            #pragma unroll
            for (int cc = 0; cc < EDGE_DIM; cc++) t = fmaf(ea[cc], Wer[cc][c], t);
            e[c] = t;
        }
        float ke0 = kk.x + e[0], ke1 = kk.y + e[1], ke2 = kk.z + e[2], ke3 = kk.w + e[3];
        float partial = q.x * ke0 + q.y * ke1 + q.z * ke2 + q.w * ke3;
        partial += __shfl_xor_sync(0xffffffffu, partial, 1);
        partial += __shfl_xor_sync(0xffffffffu, partial, 2);
        partial += __shfl_xor_sync(0xffffffffu, partial, 4);

        float logit = partial * scale;
        float mn = fmaxf(m, logit);
        float corr = __expf(m - mn);       // exp(-inf)=0 on first edge
        float p = __expf(logit - mn);
        s = s * corr + p;
        acc[0] = acc[0] * corr + p * (vv.x + e[0]);
        acc[1] = acc[1] * corr + p * (vv.y + e[1]);
        acc[2] = acc[2] * corr + p * (vv.z + e[2]);
        acc[3] = acc[3] * corr + p * (vv.w + e[3]);
        m = mn;
    }
    float inv = 1.f / fmaxf(s, 1e-9f);
    float4 outv = make_float4(acc[0] * inv, acc[1] * inv, acc[2] * inv, acc[3] * inv);
    *(float4*)&g_attn[(size_t)node * 128 + d0] = outv;
}

// ---------------- layernorm: h = LN(h + tmp) * g + b ; one warp per row ----------------
__global__ void __launch_bounds__(256) ln_kernel(
    const float* __restrict__ gam, const float* __restrict__ bet)
{
    const int row = (blockIdx.x * 256 + threadIdx.x) >> 5;
    const int lane = threadIdx.x & 31;
    if (row >= N_HITS) return;
    float v[4];
    float sum = 0.f;
    #pragma unroll
    for (int j = 0; j < 4; j++) {
        int d = lane + 32 * j;
        v[j] = g_h[(size_t)row * 128 + d] + g_tmp[(size_t)row * 128 + d];
        sum += v[j];
    }
    #pragma unroll
    for (int off = 16; off; off >>= 1) sum += __shfl_xor_sync(0xffffffffu, sum, off);
    float mu = sum * (1.f / 128.f);
    float vs = 0.f;
    #pragma unroll
    for (int j = 0; j < 4; j++) { float t = v[j] - mu; vs += t * t; }
    #pragma unroll
    for (int off = 16; off; off >>= 1) vs += __shfl_xor_sync(0xffffffffu, vs, off);
    float rstd = rsqrtf(vs * (1.f / 128.f) + LN_EPS);
    #pragma unroll
    for (int j = 0; j < 4; j++) {
        int d = lane + 32 * j;
        g_h[(size_t)row * 128 + d] = (v[j] - mu) * rstd * gam[d] + bet[d];
    }
}

// ---------------- group pooling ----------------
__global__ void pool_init_kernel() {
    int i = blockIdx.x * blockDim.x + threadIdx.x;
    int stride = gridDim.x * blockDim.x;
    for (int k = i; k < N_GROUPS * HID; k += stride)     g_gmax[k] = -INFINITY;
    for (int k = i; k < 2 * N_GROUPS * HID; k += stride) g_gsum[k] = 0.f;
    for (int k = i; k < 3 * N_GROUPS; k += stride)       g_cnt[k]  = 0.f;
}

__global__ void __launch_bounds__(128) pool_scatter_kernel(
    const float* __restrict__ x, const int* __restrict__ grp)
{
    int hit = blockIdx.x;
    int d = threadIdx.x;
    int g = grp[hit];
    float val = g_h[(size_t)hit * 128 + d];
    atomicMaxFloat(&g_gmax[g * 128 + d], val);
    int view = (int)x[(size_t)hit * 25 + 3];   // truncation toward zero like astype(int32)
    if (view == 0 || view == 1)
        atomicAdd(&g_gsum[view * N_GROUPS * HID + g * 128 + d], val);
    if (d == 0) {
        atomicAdd(&g_cnt[2 * N_GROUPS + g], 1.f);
        if (view == 0 || view == 1) atomicAdd(&g_cnt[view * N_GROUPS + g], 1.f);
    }
}

__global__ void __launch_bounds__(128) pool_finalize_kernel() {
    int g = blockIdx.x;
    int d = threadIdx.x;
    float cx = g_cnt[g], cy = g_cnt[N_GROUPS + g], ca = g_cnt[2 * N_GROUPS + g];
    float sx = g_gsum[g * 128 + d];
    float sy = g_gsum[N_GROUPS * HID + g * 128 + d];
    float px = sx / fmaxf(cx, 1.f);
    float py = sy / fmaxf(cy, 1.f);
    float hx = (cx > 0.f) ? 1.f : 0.f;
    float hy = (cy > 0.f) ? 1.f : 0.f;
    float sum_feat = px * hx + py * hy;
    float valid = fmaxf(hx + hy, 1.f);
    g_ge[g * 256 + d] = sum_feat / valid;
    g_ge[g * 256 + 128 + d] = (ca > 0.f) ? g_gmax[g * 128 + d] : 0.f;
}

// ---------------- pairwise affinity scores ----------------
__global__ void __launch_bounds__(256) scores_kernel(
    const float* __restrict__ b1, const float* __restrict__ W2, const float* __restrict__ b2)
{
    __shared__ float sA[16][129];
    __shared__ float sB[16][129];
    __shared__ float sb1[128];
    __shared__ float sW2[128];
    int tx = threadIdx.x, ty = threadIdx.y;
    int tid = ty * 16 + tx;
    int i0 = blockIdx.y * 16, j0 = blockIdx.x * 16;
    for (int t = tid; t < 16 * 128; t += 256) {
        sA[t >> 7][t & 127] = g_Aaf[(i0 + (t >> 7)) * 128 + (t & 127)];
        sB[t >> 7][t & 127] = g_Baf[(j0 + (t >> 7)) * 128 + (t & 127)];
    }
    if (tid < 128) { sb1[tid] = b1[tid]; sW2[tid] = W2[tid]; }
    __syncthreads();
    float acc = 0.f;
    #pragma unroll 8
    for (int d = 0; d < 128; d++) {
        float pre = sA[ty][d] + sB[tx][d] + sb1[d];
        acc = fmaf(fmaxf(pre, 0.f), sW2[d], acc);
    }
    g_sc[(size_t)(i0 + ty) * N_GROUPS + (j0 + tx)] = acc + b2[0];
}

__global__ void final_kernel(const int* __restrict__ batch, float* __restrict__ out) {
    int idx = blockIdx.x * blockDim.x + threadIdx.x;
    if (idx >= N_GROUPS * N_GROUPS) return;
    int i = idx >> 9, j = idx & 511;
    float sc = 0.5f * (g_sc[(size_t)i * N_GROUPS + j] + g_sc[(size_t)j * N_GROUPS + i]);
    float mask = (batch[i] == batch[j]) ? 1.f : 0.f;
    out[idx] = mask / (1.f + expf(-sc));
}

// ---------------- launch ----------------
extern "C" void kernel_launch(void* const* d_in, const int* in_sizes, int n_in,
                              void* d_out, int out_size)
{
    const float* x          = (const float*)d_in[0];
    const int*   edge_index = (const int*)  d_in[1];
    const float* edge_attr  = (const float*)d_in[2];
    const int*   grp        = (const int*)  d_in[3];
    const int*   batch      = (const int*)  d_in[4];
    const float* embed_W    = (const float*)d_in[5];
    const float* embed_b    = (const float*)d_in[6];
    const float* Wqkv       = (const float*)d_in[7];
    const float* bqkv       = (const float*)d_in[8];
    const float* We         = (const float*)d_in[9];
    const float* be         = (const float*)d_in[10];
    const float* Wo         = (const float*)d_in[11];
    const float* bo         = (const float*)d_in[12];
    const float* ln1g       = (const float*)d_in[13];
    const float* ln1b       = (const float*)d_in[14];
    const float* W1         = (const float*)d_in[15];
    const float* b1         = (const float*)d_in[16];
    const float* W2         = (const float*)d_in[17];
    const float* b2         = (const float*)d_in[18];
    const float* ln2g       = (const float*)d_in[19];
    const float* ln2b       = (const float*)d_in[20];
    const float* affW1      = (const float*)d_in[21];
    const float* affb1      = (const float*)d_in[22];
    const float* affW2      = (const float*)d_in[23];
    const float* affb2      = (const float*)d_in[24];
    float* out = (float*)d_out;

    float *p_h, *p_qkv, *p_attn, *p_ffn, *p_tmp, *p_ge, *p_A, *p_B;
    cudaGetSymbolAddress((void**)&p_h,    g_h);
    cudaGetSymbolAddress((void**)&p_qkv,  g_qkv);
    cudaGetSymbolAddress((void**)&p_attn, g_attn);
    cudaGetSymbolAddress((void**)&p_ffn,  g_ffn);
    cudaGetSymbolAddress((void**)&p_tmp,  g_tmp);
    cudaGetSymbolAddress((void**)&p_ge,   g_ge);
    cudaGetSymbolAddress((void**)&p_A,    g_Aaf);
    cudaGetSymbolAddress((void**)&p_B,    g_Baf);

    // CSR build
    zero_deg_kernel<<<N_HITS / 256, 256>>>();
    hist_kernel<<<N_EDGES / 256, 256>>>(edge_index);
    scan_kernel<<<1, 1024>>>();
    copy_cursor_kernel<<<N_HITS / 256, 256>>>();
    scatter_kernel<<<N_EDGES / 256, 256>>>(edge_index);

    // embed
    embed_kernel<<<N_HITS / 8, 128>>>(x, embed_W, embed_b);

    for (int l = 0; l < LAYERS; l++) {
        // qkv = h @ Wqkv + b
        tf32_gemm_kernel<<<dim3(384 / GBN, N_HITS / GBM), 256>>>(
            p_h, Wqkv + (size_t)l * HID * 3 * HID, bqkv + l * 3 * HID, p_qkv,
            N_HITS, 3 * HID, HID, 0);
        // edge attention -> g_attn
        attn_kernel<<<N_HITS / 8, 256>>>(edge_attr,
            We + (size_t)l * EDGE_DIM * HID, be + l * HID);
        // attn @ Wo + bo -> tmp
        tf32_gemm_kernel<<<dim3(HID / GBN, N_HITS / GBM), 256>>>(
            p_attn, Wo + (size_t)l * HID * HID, bo + l * HID, p_tmp,
            N_HITS, HID, HID, 0);
        // h = LN1(h + tmp)
        ln_kernel<<<N_HITS / 8, 256>>>(ln1g + l * HID, ln1b + l * HID);
        // ffn hidden = relu(h @ W1 + b1)
        tf32_gemm_kernel<<<dim3(FFN_DIM / GBN, N_HITS / GBM), 256>>>(
            p_h, W1 + (size_t)l * HID * FFN_DIM, b1 + l * FFN_DIM, p_ffn,
            N_HITS, FFN_DIM, HID, 1);
        // tmp = ffn @ W2 + b2
        tf32_gemm_kernel<<<dim3(HID / GBN, N_HITS / GBM), 256>>>(
            p_ffn, W2 + (size_t)l * FFN_DIM * HID, b2 + l * HID, p_tmp,
            N_HITS, HID, FFN_DIM, 0);
        // h = LN2(h + tmp)
        ln_kernel<<<N_HITS / 8, 256>>>(ln2g + l * HID, ln2b + l * HID);
    }

    // pooling -> ge [512, 256]
    pool_init_kernel<<<256, 256>>>();
    pool_scatter_kernel<<<N_HITS, 128>>>(x, grp);
    pool_finalize_kernel<<<N_GROUPS, 128>>>();

    // affinity: A = ge @ W1a, B = ge @ W1b   (bias folded into scores kernel)
    tf32_gemm_kernel<<<dim3(HID / GBN, N_GROUPS / GBM), 256>>>(
        p_ge, affW1, nullptr, p_A, N_GROUPS, HID, 2 * HID, 0);
    tf32_gemm_kernel<<<dim3(HID / GBN, N_GROUPS / GBM), 256>>>(
        p_ge, affW1 + (size_t)2 * HID * HID, nullptr, p_B, N_GROUPS, HID, 2 * HID, 0);

    scores_kernel<<<dim3(N_GROUPS / 16, N_GROUPS / 16), dim3(16, 16)>>>(affb1, affW2, affb2);
    final_kernel<<<(N_GROUPS * N_GROUPS) / 256, 256>>>(batch, out);
}

// round 4
// speedup vs baseline: 1.7911x; 1.6150x over previous
#include <cuda_runtime.h>
#include <math.h>
#include <stdint.h>

#define N_HITS   16384
#define N_EDGES  262144
#define N_GROUPS 512
#define HID      128
#define HEADS    4
#define DH       32
#define LAYERS   3
#define EDGE_DIM 5
#define FFN_DIM  512
#define LN_EPS   1e-5f

// ---------------- scratch (static device globals; no allocation) ----------------
__device__ float g_h   [N_HITS * HID];
__device__ float g_qkv [N_HITS * 3 * HID];
__device__ float g_attn[N_HITS * HID];
__device__ float g_ffn [N_HITS * FFN_DIM];
__device__ int   g_deg [N_HITS];
__device__ int   g_rowptr[N_HITS + 1];
__device__ int   g_cursor[N_HITS];
__device__ int   g_eid [N_EDGES];
__device__ int   g_esrc[N_EDGES];
__device__ int   g_bsum[64];
__device__ int   g_boff[64];
__device__ float g_gmax[N_GROUPS * HID];
__device__ float g_gsum[2 * N_GROUPS * HID];
__device__ float g_cnt [3 * N_GROUPS];
__device__ float g_ge  [N_GROUPS * 2 * HID];
__device__ float g_Aaf [N_GROUPS * HID];
__device__ float g_Baf [N_GROUPS * HID];
__device__ float g_sc  [N_GROUPS * N_GROUPS];

// ---------------- helpers ----------------
__device__ __forceinline__ void atomicMaxFloat(float* addr, float value) {
    if (value >= 0.f)
        atomicMax((int*)addr, __float_as_int(value));
    else
        atomicMin((unsigned int*)addr, __float_as_uint(value));
}

__device__ __forceinline__ uint32_t smem_u32(const void* p) {
    uint32_t a;
    asm("{ .reg .u64 t; cvta.to.shared.u64 t, %1; cvt.u32.u64 %0, t; }" : "=r"(a) : "l"(p));
    return a;
}

__device__ __forceinline__ void cpa16(uint32_t dst, const float* src) {
    asm volatile("cp.async.cg.shared.global [%0], [%1], 16;\n" :: "r"(dst), "l"(src));
}
__device__ __forceinline__ void cpa_commit() {
    asm volatile("cp.async.commit_group;\n" ::);
}

__device__ __forceinline__ void mma_tf32(float* d, const uint32_t* a, const uint32_t* b) {
    asm volatile(
        "mma.sync.aligned.m16n8k8.row.col.f32.tf32.tf32.f32 "
        "{%0,%1,%2,%3}, {%4,%5,%6,%7}, {%8,%9}, {%0,%1,%2,%3};"
        : "+f"(d[0]), "+f"(d[1]), "+f"(d[2]), "+f"(d[3])
        : "r"(a[0]), "r"(a[1]), "r"(a[2]), "r"(a[3]),
          "r"(b[0]), "r"(b[1]));
}

// ---------------- CSR build ----------------
__global__ void zero_deg_kernel() {
    int i = blockIdx.x * blockDim.x + threadIdx.x;
    if (i < N_HITS) g_deg[i] = 0;
}

__global__ void hist_kernel(const int* __restrict__ ei) {
    int e = blockIdx.x * blockDim.x + threadIdx.x;
    if (e < N_EDGES) atomicAdd(&g_deg[ei[N_EDGES + e]], 1);
}

__global__ void scan1_kernel() {          // 64 blocks x 256
    __shared__ int sh[8];
    int tid = threadIdx.x;
    int v = g_deg[blockIdx.x * 256 + tid];
    #pragma unroll
    for (int off = 16; off; off >>= 1) v += __shfl_xor_sync(0xffffffffu, v, off);
    if ((tid & 31) == 0) sh[tid >> 5] = v;
    __syncthreads();
    if (tid == 0) {
        int s = 0;
        #pragma unroll
        for (int w = 0; w < 8; w++) s += sh[w];
        g_bsum[blockIdx.x] = s;
    }
}

__global__ void scan2_kernel() {          // 1 block x 64
    __shared__ int sh[64];
    int t = threadIdx.x;
    int v = g_bsum[t];
    sh[t] = v;
    __syncthreads();
    for (int off = 1; off < 64; off <<= 1) {
        int a = (t >= off) ? sh[t - off] : 0;
        __syncthreads();
        sh[t] += a;
        __syncthreads();
    }
    g_boff[t] = sh[t] - v;
    if (t == 63) g_rowptr[N_HITS] = sh[63];
}

__global__ void scan3_kernel() {          // 64 blocks x 256
    __shared__ int sh[256];
    int b = blockIdx.x, t = threadIdx.x;
    int i = b * 256 + t;
    int v = g_deg[i];
    sh[t] = v;
    __syncthreads();
    for (int off = 1; off < 256; off <<= 1) {
        int a = (t >= off) ? sh[t - off] : 0;
        __syncthreads();
        sh[t] += a;
        __syncthreads();
    }
    int excl = g_boff[b] + sh[t] - v;
    g_rowptr[i] = excl;
    g_cursor[i] = excl;
}

__global__ void scatter_kernel(const int* __restrict__ ei) {
    int e = blockIdx.x * blockDim.x + threadIdx.x;
    if (e < N_EDGES) {
        int dstn = ei[N_EDGES + e];
        int pos = atomicAdd(&g_cursor[dstn], 1);
        g_eid[pos]  = e;
        g_esrc[pos] = ei[e];
    }
}

// ---------------- embed: h = x @ W(25x128) + b ----------------
__global__ void __launch_bounds__(128) embed_kernel(
    const float* __restrict__ x, const float* __restrict__ W, const float* __restrict__ b)
{
    __shared__ float sW[25 * 128];
    __shared__ float sx[8][25];
    int tid = threadIdx.x;
    for (int i = tid; i < 25 * 128; i += 128) sW[i] = W[i];
    int r0 = blockIdx.x * 8;
    for (int i = tid; i < 8 * 25; i += 128)
        sx[i / 25][i % 25] = x[(size_t)(r0 + i / 25) * 25 + (i % 25)];
    __syncthreads();
    float bb = b[tid];
    for (int r = 0; r < 8; r++) {
        float acc = bb;
        #pragma unroll
        for (int c = 0; c < 25; c++) acc = fmaf(sx[r][c], sW[c * 128 + tid], acc);
        g_h[(size_t)(r0 + r) * 128 + tid] = acc;
    }
}

// ---------------- TF32 GEMM, cp.async double-buffered ----------------
// C[MxN] = A[MxK] @ B[KxN]. BM=128 BN=128 BK=32, 256 threads (8 warps 2x4, warp 64x32).
// mode 0: +bias (bias may be null)    mode 1: +bias, relu
// mode 2: out = LN(res + gemm + bias) * gam + bet   (requires N==128, single N-tile)
#define ASTRIDE 36
#define BSTRIDE 136
#define A_OFF0 0
#define A_OFF1 18432
#define B_OFF0 36864
#define B_OFF1 54272
#define GEMM_SMEM 71680

__global__ void __launch_bounds__(256, 2) gemm_kernel(
    const float* __restrict__ A, const float* __restrict__ B,
    const float* __restrict__ bias, float* __restrict__ C,
    int M, int N, int K, int mode,
    const float* __restrict__ res, const float* __restrict__ gam, const float* __restrict__ bet)
{
    extern __shared__ char sm[];
    const uint32_t sbase = smem_u32(sm);
    const int tid  = threadIdx.x;
    const int wid  = tid >> 5;
    const int lane = tid & 31;
    const int wm = wid & 1, wn = wid >> 1;
    const int g = lane >> 2, r = lane & 3;
    const int m0 = blockIdx.y * 128;
    const int n0 = blockIdx.x * 128;
    const int arow = tid >> 1, akh = (tid & 1) * 16;
    const int brow = tid >> 3, bcol = (tid & 7) * 16;
    const int nk = K >> 5;

    float acc[4][4][4] = {};

    // stage loader
    const uint32_t aaddr = sbase + (uint32_t)(arow * ASTRIDE + akh) * 4;
    const uint32_t baddr = sbase + (uint32_t)(brow * BSTRIDE + bcol) * 4;
    const float* Abase = A + (size_t)(m0 + arow) * K + akh;
    const float* Bbase = B + (size_t)brow * N + n0 + bcol;

    {   // prefetch stage 0
        const float* Ap = Abase;
        const float* Bp = Bbase;
        #pragma unroll
        for (int i = 0; i < 4; i++) cpa16(aaddr + A_OFF0 + i * 16, Ap + i * 4);
        #pragma unroll
        for (int i = 0; i < 4; i++) cpa16(baddr + B_OFF0 + i * 16, Bp + i * 4);
        cpa_commit();
    }

    for (int t = 0; t < nk; t++) {
        if (t + 1 < nk) {
            const uint32_t ao = ((t + 1) & 1) ? A_OFF1 : A_OFF0;
            const uint32_t bo = ((t + 1) & 1) ? B_OFF1 : B_OFF0;
            const float* Ap = Abase + (t + 1) * 32;
            const float* Bp = Bbase + (size_t)(t + 1) * 32 * N;
            #pragma unroll
            for (int i = 0; i < 4; i++) cpa16(aaddr + ao + i * 16, Ap + i * 4);
            #pragma unroll
            for (int i = 0; i < 4; i++) cpa16(baddr + bo + i * 16, Bp + i * 4);
            cpa_commit();
            asm volatile("cp.async.wait_group 1;\n" ::);
        } else {
            asm volatile("cp.async.wait_group 0;\n" ::);
        }
        __syncthreads();

        const float* sA = (const float*)(sm + ((t & 1) ? A_OFF1 : A_OFF0));
        const float* sB = (const float*)(sm + ((t & 1) ? B_OFF1 : B_OFF0));
        #pragma unroll
        for (int ks = 0; ks < 4; ks++) {
            const int kk = ks * 8;
            uint32_t af[4][4], bf[4][2];
            #pragma unroll
            for (int mt = 0; mt < 4; mt++) {
                int rb = wm * 64 + mt * 16;
                af[mt][0] = __float_as_uint(sA[(rb + g    ) * ASTRIDE + kk + r    ]);
                af[mt][1] = __float_as_uint(sA[(rb + g + 8) * ASTRIDE + kk + r    ]);
                af[mt][2] = __float_as_uint(sA[(rb + g    ) * ASTRIDE + kk + r + 4]);
                af[mt][3] = __float_as_uint(sA[(rb + g + 8) * ASTRIDE + kk + r + 4]);
            }
            #pragma unroll
            for (int nt = 0; nt < 4; nt++) {
                int cb = wn * 32 + nt * 8;
                bf[nt][0] = __float_as_uint(sB[(kk + r    ) * BSTRIDE + cb + g]);
                bf[nt][1] = __float_as_uint(sB[(kk + r + 4) * BSTRIDE + cb + g]);
            }
            #pragma unroll
            for (int mt = 0; mt < 4; mt++)
                #pragma unroll
                for (int nt = 0; nt < 4; nt++)
                    mma_tf32(acc[mt][nt], af[mt], bf[nt]);
        }
        __syncthreads();
    }

    if (mode < 2) {
        #pragma unroll
        for (int mt = 0; mt < 4; mt++) {
            int row_a = m0 + wm * 64 + mt * 16 + g;
            int row_b = row_a + 8;
            #pragma unroll
            for (int nt = 0; nt < 4; nt++) {
                int col = n0 + wn * 32 + nt * 8 + 2 * r;
                float b0 = 0.f, b1 = 0.f;
                if (bias) { b0 = bias[col]; b1 = bias[col + 1]; }
                float v0 = acc[mt][nt][0] + b0;
                float v1 = acc[mt][nt][1] + b1;
                float v2 = acc[mt][nt][2] + b0;
                float v3 = acc[mt][nt][3] + b1;
                if (mode == 1) {
                    v0 = fmaxf(v0, 0.f); v1 = fmaxf(v1, 0.f);
                    v2 = fmaxf(v2, 0.f); v3 = fmaxf(v3, 0.f);
                }
                *(float2*)&C[(size_t)row_a * N + col] = make_float2(v0, v1);
                *(float2*)&C[(size_t)row_b * N + col] = make_float2(v2, v3);
            }
        }
    } else {
        // stage to smem, per-row fused residual + layernorm (N == 128)
        float* sC = (float*)sm;
        #pragma unroll
        for (int mt = 0; mt < 4; mt++) {
            int lr = wm * 64 + mt * 16 + g;
            #pragma unroll
            for (int nt = 0; nt < 4; nt++) {
                int lc = wn * 32 + nt * 8 + 2 * r;
                sC[lr * 132 + lc]           = acc[mt][nt][0];
                sC[lr * 132 + lc + 1]       = acc[mt][nt][1];
                sC[(lr + 8) * 132 + lc]     = acc[mt][nt][2];
                sC[(lr + 8) * 132 + lc + 1] = acc[mt][nt][3];
            }
        }
        __syncthreads();
        if (tid < 128) {
            int row = m0 + tid;
            const float* rp = res + (size_t)row * 128;
            float sum = 0.f, sq = 0.f;
            #pragma unroll 8
            for (int c = 0; c < 32; c++) {
                float4 v  = *(float4*)&sC[tid * 132 + c * 4];
                float4 bb = *(const float4*)&bias[c * 4];
                float4 hh = *(const float4*)&rp[c * 4];
                v.x += bb.x + hh.x; v.y += bb.y + hh.y;
                v.z += bb.z + hh.z; v.w += bb.w + hh.w;
                *(float4*)&sC[tid * 132 + c * 4] = v;
                sum += v.x + v.y + v.z + v.w;
                sq  += v.x * v.x + v.y * v.y + v.z * v.z + v.w * v.w;
            }
            float mu = sum * (1.f / 128.f);
            float var = sq * (1.f / 128.f) - mu * mu;
            float rstd = rsqrtf(var + LN_EPS);
            float* op = C + (size_t)row * 128;
            #pragma unroll 8
            for (int c = 0; c < 32; c++) {
                float4 v  = *(float4*)&sC[tid * 132 + c * 4];
                float4 gm = *(const float4*)&gam[c * 4];
                float4 bt = *(const float4*)&bet[c * 4];
                float4 o;
                o.x = (v.x - mu) * rstd * gm.x + bt.x;
                o.y = (v.y - mu) * rstd * gm.y + bt.y;
                o.z = (v.z - mu) * rstd * gm.z + bt.z;
                o.w = (v.w - mu) * rstd * gm.w + bt.w;
                *(float4*)&op[c * 4] = o;
            }
        }
    }
}

// ---------------- edge attention: one warp per destination node, online softmax ----------------
__global__ void __launch_bounds__(256) attn_kernel(
    const float* __restrict__ edge_attr,
    const float* __restrict__ We, const float* __restrict__ be)
{
    const int node = (blockIdx.x * 256 + threadIdx.x) >> 5;
    const int lane = threadIdx.x & 31;
    if (node >= N_HITS) return;

    const int d0 = 4 * lane;
    float Wer[EDGE_DIM][4], ber[4];
    #pragma unroll
    for (int c = 0; c < 4; c++) {
        ber[c] = be[d0 + c];
        #pragma unroll
        for (int cc = 0; cc < EDGE_DIM; cc++) Wer[cc][c] = We[cc * HID + d0 + c];
    }
    float4 q = *(const float4*)&g_qkv[(size_t)node * 384 + d0];

    float m = -INFINITY, s = 0.f;
    float acc[4] = {0.f, 0.f, 0.f, 0.f};

    const int beg = g_rowptr[node], end = g_rowptr[node + 1];
    const float scale = 0.17677669529663687f;

    for (int idx = beg; idx < end; idx++) {
        int eid = g_eid[idx];
        int src = g_esrc[idx];
        float ea[EDGE_DIM];
        #pragma unroll
        for (int cc = 0; cc < EDGE_DIM; cc++) ea[cc] = edge_attr[(size_t)eid * EDGE_DIM + cc];
        float4 kk = *(const float4*)&g_qkv[(size_t)src * 384 + 128 + d0];
        float4 vv = *(const float4*)&g_qkv[(size_t)src * 384 + 256 + d0];

        float e[4];
        #pragma unroll
        for (int c = 0; c < 4; c++) {
            float t = ber[c];
            #pragma unroll
            for (int cc = 0; cc < EDGE_DIM; cc++) t = fmaf(ea[cc], Wer[cc][c], t);
            e[c] = t;
        }
        float partial = q.x * (kk.x + e[0]) + q.y * (kk.y + e[1])
                      + q.z * (kk.z + e[2]) + q.w * (kk.w + e[3]);
        partial += __shfl_xor_sync(0xffffffffu, partial, 1);
        partial += __shfl_xor_sync(0xffffffffu, partial, 2);
        partial += __shfl_xor_sync(0xffffffffu, partial, 4);

        float logit = partial * scale;
        float mn = fmaxf(m, logit);
        float corr = __expf(m - mn);
        float p = __expf(logit - mn);
        s = s * corr + p;
        acc[0] = acc[0] * corr + p * (vv.x + e[0]);
        acc[1] = acc[1] * corr + p * (vv.y + e[1]);
        acc[2] = acc[2] * corr + p * (vv.z + e[2]);
        acc[3] = acc[3] * corr + p * (vv.w + e[3]);
        m = mn;
    }
    float inv = 1.f / fmaxf(s, 1e-9f);
    *(float4*)&g_attn[(size_t)node * 128 + d0] =
        make_float4(acc[0] * inv, acc[1] * inv, acc[2] * inv, acc[3] * inv);
}

// ---------------- group pooling ----------------
__global__ void pool_init_kernel() {
    int i = blockIdx.x * blockDim.x + threadIdx.x;
    int stride = gridDim.x * blockDim.x;
    for (int k = i; k < N_GROUPS * HID; k += stride)     g_gmax[k] = -INFINITY;
    for (int k = i; k < 2 * N_GROUPS * HID; k += stride) g_gsum[k] = 0.f;
    for (int k = i; k < 3 * N_GROUPS; k += stride)       g_cnt[k]  = 0.f;
}

__global__ void __launch_bounds__(128) pool_scatter_kernel(
    const float* __restrict__ x, const int* __restrict__ grp)
{
    int hit = blockIdx.x;
    int d = threadIdx.x;
    int g = grp[hit];
    float val = g_h[(size_t)hit * 128 + d];
    atomicMaxFloat(&g_gmax[g * 128 + d], val);
    int view = (int)x[(size_t)hit * 25 + 3];
    if (view == 0 || view == 1)
        atomicAdd(&g_gsum[view * N_GROUPS * HID + g * 128 + d], val);
    if (d == 0) {
        atomicAdd(&g_cnt[2 * N_GROUPS + g], 1.f);
        if (view == 0 || view == 1) atomicAdd(&g_cnt[view * N_GROUPS + g], 1.f);
    }
}

__global__ void __launch_bounds__(128) pool_finalize_kernel() {
    int g = blockIdx.x;
    int d = threadIdx.x;
    float cx = g_cnt[g], cy = g_cnt[N_GROUPS + g], ca = g_cnt[2 * N_GROUPS + g];
    float sx = g_gsum[g * 128 + d];
    float sy = g_gsum[N_GROUPS * HID + g * 128 + d];
    float px = sx / fmaxf(cx, 1.f);
    float py = sy / fmaxf(cy, 1.f);
    float hx = (cx > 0.f) ? 1.f : 0.f;
    float hy = (cy > 0.f) ? 1.f : 0.f;
    float sum_feat = px * hx + py * hy;
    float valid = fmaxf(hx + hy, 1.f);
    g_ge[g * 256 + d] = sum_feat / valid;
    g_ge[g * 256 + 128 + d] = (ca > 0.f) ? g_gmax[g * 128 + d] : 0.f;
}

// ---------------- pairwise affinity scores ----------------
__global__ void __launch_bounds__(256) scores_kernel(
    const float* __restrict__ b1, const float* __restrict__ W2, const float* __restrict__ b2)
{
    __shared__ float sA[16][129];
    __shared__ float sB[16][129];
    __shared__ float sb1[128];
    __shared__ float sW2[128];
    int tx = threadIdx.x, ty = threadIdx.y;
    int tid = ty * 16 + tx;
    int i0 = blockIdx.y * 16, j0 = blockIdx.x * 16;
    for (int t = tid; t < 16 * 128; t += 256) {
        sA[t >> 7][t & 127] = g_Aaf[(i0 + (t >> 7)) * 128 + (t & 127)];
        sB[t >> 7][t & 127] = g_Baf[(j0 + (t >> 7)) * 128 + (t & 127)];
    }
    if (tid < 128) { sb1[tid] = b1[tid]; sW2[tid] = W2[tid]; }
    __syncthreads();
    float acc = 0.f;
    #pragma unroll 8
    for (int d = 0; d < 128; d++) {
        float pre = sA[ty][d] + sB[tx][d] + sb1[d];
        acc = fmaf(fmaxf(pre, 0.f), sW2[d], acc);
    }
    g_sc[(size_t)(i0 + ty) * N_GROUPS + (j0 + tx)] = acc + b2[0];
}

__global__ void final_kernel(const int* __restrict__ batch, float* __restrict__ out) {
    int idx = blockIdx.x * blockDim.x + threadIdx.x;
    if (idx >= N_GROUPS * N_GROUPS) return;
    int i = idx >> 9, j = idx & 511;
    float sc = 0.5f * (g_sc[(size_t)i * N_GROUPS + j] + g_sc[(size_t)j * N_GROUPS + i]);
    float mask = (batch[i] == batch[j]) ? 1.f : 0.f;
    out[idx] = mask / (1.f + expf(-sc));
}

// ---------------- launch ----------------
extern "C" void kernel_launch(void* const* d_in, const int* in_sizes, int n_in,
                              void* d_out, int out_size)
{
    const float* x          = (const float*)d_in[0];
    const int*   edge_index = (const int*)  d_in[1];
    const float* edge_attr  = (const float*)d_in[2];
    const int*   grp        = (const int*)  d_in[3];
    const int*   batch      = (const int*)  d_in[4];
    const float* embed_W    = (const float*)d_in[5];
    const float* embed_b    = (const float*)d_in[6];
    const float* Wqkv       = (const float*)d_in[7];
    const float* bqkv       = (const float*)d_in[8];
    const float* We         = (const float*)d_in[9];
    const float* be         = (const float*)d_in[10];
    const float* Wo         = (const float*)d_in[11];
    const float* bo         = (const float*)d_in[12];
    const float* ln1g       = (const float*)d_in[13];
    const float* ln1b       = (const float*)d_in[14];
    const float* W1         = (const float*)d_in[15];
    const float* b1         = (const float*)d_in[16];
    const float* W2         = (const float*)d_in[17];
    const float* b2         = (const float*)d_in[18];
    const float* ln2g       = (const float*)d_in[19];
    const float* ln2b       = (const float*)d_in[20];
    const float* affW1      = (const float*)d_in[21];
    const float* affb1      = (const float*)d_in[22];
    const float* affW2      = (const float*)d_in[23];
    const float* affb2      = (const float*)d_in[24];
    float* out = (float*)d_out;

    float *p_h, *p_qkv, *p_attn, *p_ffn, *p_ge, *p_A, *p_B;
    cudaGetSymbolAddress((void**)&p_h,    g_h);
    cudaGetSymbolAddress((void**)&p_qkv,  g_qkv);
    cudaGetSymbolAddress((void**)&p_attn, g_attn);
    cudaGetSymbolAddress((void**)&p_ffn,  g_ffn);
    cudaGetSymbolAddress((void**)&p_ge,   g_ge);
    cudaGetSymbolAddress((void**)&p_A,    g_Aaf);
    cudaGetSymbolAddress((void**)&p_B,    g_Baf);

    cudaFuncSetAttribute(gemm_kernel, cudaFuncAttributeMaxDynamicSharedMemorySize, GEMM_SMEM);

    // slots 0..4, slot 5 = first qkv GEMM (ncu -s 5 -c 1 captures it)
    embed_kernel<<<N_HITS / 8, 128>>>(x, embed_W, embed_b);                    // 0
    zero_deg_kernel<<<N_HITS / 256, 256>>>();                                  // 1
    hist_kernel<<<N_EDGES / 256, 256>>>(edge_index);                           // 2
    scan1_kernel<<<64, 256>>>();                                               // 3
    scan2_kernel<<<1, 64>>>();                                                 // 4
    gemm_kernel<<<dim3(3, 128), 256, GEMM_SMEM>>>(                             // 5
        p_h, Wqkv, bqkv, p_qkv, N_HITS, 384, 128, 0, nullptr, nullptr, nullptr);
    scan3_kernel<<<64, 256>>>();                                               // 6
    scatter_kernel<<<N_EDGES / 256, 256>>>(edge_index);                        // 7

    for (int l = 0; l < LAYERS; l++) {
        if (l > 0) {
            gemm_kernel<<<dim3(3, 128), 256, GEMM_SMEM>>>(
                p_h, Wqkv + (size_t)l * 49152, bqkv + l * 384, p_qkv,
                N_HITS, 384, 128, 0, nullptr, nullptr, nullptr);
        }
        attn_kernel<<<N_HITS / 8, 256>>>(edge_attr,
            We + (size_t)l * EDGE_DIM * HID, be + l * HID);
        // h = LN1(h + attn @ Wo + bo)   (fused)
        gemm_kernel<<<dim3(1, 128), 256, GEMM_SMEM>>>(
            p_attn, Wo + (size_t)l * 16384, bo + l * 128, p_h,
            N_HITS, 128, 128, 2, p_h, ln1g + l * 128, ln1b + l * 128);
        // ffn = relu(h @ W1 + b1)
        gemm_kernel<<<dim3(4, 128), 256, GEMM_SMEM>>>(
            p_h, W1 + (size_t)l * 65536, b1 + l * 512, p_ffn,
            N_HITS, 512, 128, 1, nullptr, nullptr, nullptr);
        // h = LN2(h + ffn @ W2 + b2)   (fused)
        gemm_kernel<<<dim3(1, 128), 256, GEMM_SMEM>>>(
            p_ffn, W2 + (size_t)l * 65536, b2 + l * 128, p_h,
            N_HITS, 128, 512, 2, p_h, ln2g + l * 128, ln2b + l * 128);
    }

    // pooling -> ge [512, 256]
    pool_init_kernel<<<256, 256>>>();
    pool_scatter_kernel<<<N_HITS, 128>>>(x, grp);
    pool_finalize_kernel<<<N_GROUPS, 128>>>();

    // affinity projections: A = ge @ W1a, B = ge @ W1b
    gemm_kernel<<<dim3(1, 4), 256, GEMM_SMEM>>>(
        p_ge, affW1, nullptr, p_A, N_GROUPS, 128, 256, 0, nullptr, nullptr, nullptr);
    gemm_kernel<<<dim3(1, 4), 256, GEMM_SMEM>>>(
        p_ge, affW1 + (size_t)256 * 128, nullptr, p_B, N_GROUPS, 128, 256, 0, nullptr, nullptr, nullptr);

    scores_kernel<<<dim3(N_GROUPS / 16, N_GROUPS / 16), dim3(16, 16)>>>(affb1, affW2, affb2);
    final_kernel<<<(N_GROUPS * N_GROUPS) / 256, 256>>>(batch, out);
}